// round 14
// baseline (speedup 1.0000x reference)
#include <cuda_runtime.h>

// WavUnPacking: inverse Haar DWT (db1, per-2x2 butterfly + interleave).
// x: (B=8, C=256, H=128, W=128) fp32 -> out: (B=8, C4=64, 2H=256, 2W=256) fp32
//
// FINAL (converged; session best 43.49us, noise band ±0.25us measured on
// byte-identical resubmissions R9/R13).
// Thread-per-output-f4-column mapping:
//  - 4 dense LDG.64 reads (one float2 per subband; full 128B lines per warp)
//  - 2 dense STG.128 writes (512B contiguous per warp instr; lane j -> f4 col j)
//  - __ldg loads, __stcs stores, block=512, 24 regs.
// 256 MiB compulsory traffic in ~36.1us kernel = 7.44 TB/s effective (~93% of
// 8 TB/s spec). Measured-neutral: MLP depth (R5), persistent grid (R6),
// block 256/512/1024 (R3/R7/R12), load/store cache-hint matrix (R3/R4/R7/R8).
// Structural win: R4 dense-store remap (DRAM 63%->75%, kernel 42.9->36.3us).
// Rejected by analysis: LDG.128 variant (reintroduces half-dense stores),
// shuffle exchange (zero wavefront gain), TMA (same LTS path), L2 tiling
// (touch-once data). Remaining gap = HBM R/W-turnaround physics.

static constexpr int B  = 8;
static constexpr int C4 = 64;   // output channels
static constexpr int H  = 128;
static constexpr int J  = 64;   // output float4 columns per row

__global__ void __launch_bounds__(512)
wav_unpack_kernel(const float2* __restrict__ x, float4* __restrict__ out)
{
    int idx = blockIdx.x * blockDim.x + threadIdx.x;
    // idx layout: [bc (512)][h (128)][j (64)]
    int j  = idx & (J - 1);           // output f4 column
    int h  = (idx >> 6) & (H - 1);
    int bc = idx >> 13;               // b*64 + c, 0..511
    int b  = bc >> 6;

    // input channel index: b*256 + c = bc + 192*b (single IMAD)
    const int plane2 = H * 64;                     // float2 per channel plane
    int base = ((bc + 192 * b) * H + h) * 64 + j;  // float2 index of w=2j
    const int cs = C4 * plane2;                    // subband stride (float2)

    // 4 independent dense loads
    float2 ll = __ldg(&x[base]);
    float2 lh = __ldg(&x[base + cs]);
    float2 hl = __ldg(&x[base + 2 * cs]);
    float2 hh = __ldg(&x[base + 3 * cs]);

    float4 top, bot;
    {
        float a, bb, cc, d;
        a = ll.x; bb = lh.x; cc = hl.x; d = hh.x;
        top.x = 0.5f*(a+bb+cc+d);  top.y = 0.5f*(a+bb-cc-d);
        bot.x = 0.5f*(a-bb+cc-d);  bot.y = 0.5f*(a-bb-cc+d);
        a = ll.y; bb = lh.y; cc = hl.y; d = hh.y;
        top.z = 0.5f*(a+bb+cc+d);  top.w = 0.5f*(a+bb-cc-d);
        bot.z = 0.5f*(a-bb+cc-d);  bot.w = 0.5f*(a-bb-cc+d);
    }

    // output: 256 rows * 64 float4/row per (b,c) plane; rows 2h, 2h+1
    int otop = (bc * 256 + 2 * h) * 64 + j;
    __stcs(&out[otop],      top);   // dense across warp: lane j -> f4 column j
    __stcs(&out[otop + 64], bot);
}

extern "C" void kernel_launch(void* const* d_in, const int* in_sizes, int n_in,
                              void* d_out, int out_size)
{
    const float2* x = (const float2*)d_in[0];
    float4* out = (float4*)d_out;

    int total_threads = B * C4 * H * J;  // 4,194,304
    int block = 512;
    int grid = total_threads / block;    // 8192
    wav_unpack_kernel<<<grid, block>>>(x, out);
}

// round 15
// speedup vs baseline: 1.0074x; 1.0074x over previous
#include <cuda_runtime.h>

// WavUnPacking: inverse Haar DWT (db1, per-2x2 butterfly + interleave).
// x: (B=8, C=256, H=128, W=128) fp32 -> out: (B=8, C4=64, 2H=256, 2W=256) fp32
//
// CONVERGED FINAL — session best 43.49us; noise band ±0.3us measured across
// three byte-identical submissions (R9/R13/R14: 43.49/43.74/43.78).
//
// Thread-per-output-f4-column mapping:
//  - 4 dense LDG.64 reads (one float2 per subband; full 128B lines per warp)
//  - 2 dense STG.128 writes (512B contiguous per warp instr; lane j -> f4 col j)
//  - __ldg loads, __stcs stores, block=512, 24 regs, occ ~75%.
//
// 256 MiB compulsory traffic in ~36.1us kernel = ~7.4 TB/s effective
// (~93% of 8 TB/s spec). Measured-neutral levers: MLP depth (R5), persistent
// grid (R6), block 256/512/1024 (R3/R7/R12), load/store cache-hint matrix
// (R3/R4/R7/R8), IMAD fold (R9). Structural win: R4 dense-store remap
// (DRAM 63%->75%, kernel 42.9->36.3us). Analysis-rejected: LDG.128 variant
// (reintroduces half-dense stores), shuffle exchange (no wavefront-per-byte
// change), TMA (pattern-independent LTS path), L2 tiling (touch-once data).
// Remaining gap to spec = HBM read/write-turnaround physics.

static constexpr int B  = 8;
static constexpr int C4 = 64;   // output channels
static constexpr int H  = 128;
static constexpr int J  = 64;   // output float4 columns per row

__global__ void __launch_bounds__(512)
wav_unpack_kernel(const float2* __restrict__ x, float4* __restrict__ out)
{
    int idx = blockIdx.x * blockDim.x + threadIdx.x;
    // idx layout: [bc (512)][h (128)][j (64)]
    int j  = idx & (J - 1);           // output f4 column
    int h  = (idx >> 6) & (H - 1);
    int bc = idx >> 13;               // b*64 + c, 0..511
    int b  = bc >> 6;

    // input channel index: b*256 + c = bc + 192*b (single IMAD)
    const int plane2 = H * 64;                     // float2 per channel plane
    int base = ((bc + 192 * b) * H + h) * 64 + j;  // float2 index of w=2j
    const int cs = C4 * plane2;                    // subband stride (float2)

    // 4 independent dense loads
    float2 ll = __ldg(&x[base]);
    float2 lh = __ldg(&x[base + cs]);
    float2 hl = __ldg(&x[base + 2 * cs]);
    float2 hh = __ldg(&x[base + 3 * cs]);

    float4 top, bot;
    {
        float a, bb, cc, d;
        a = ll.x; bb = lh.x; cc = hl.x; d = hh.x;
        top.x = 0.5f*(a+bb+cc+d);  top.y = 0.5f*(a+bb-cc-d);
        bot.x = 0.5f*(a-bb+cc-d);  bot.y = 0.5f*(a-bb-cc+d);
        a = ll.y; bb = lh.y; cc = hl.y; d = hh.y;
        top.z = 0.5f*(a+bb+cc+d);  top.w = 0.5f*(a+bb-cc-d);
        bot.z = 0.5f*(a-bb+cc-d);  bot.w = 0.5f*(a-bb-cc+d);
    }

    // output: 256 rows * 64 float4/row per (b,c) plane; rows 2h, 2h+1
    int otop = (bc * 256 + 2 * h) * 64 + j;
    __stcs(&out[otop],      top);   // dense across warp: lane j -> f4 column j
    __stcs(&out[otop + 64], bot);
}

extern "C" void kernel_launch(void* const* d_in, const int* in_sizes, int n_in,
                              void* d_out, int out_size)
{
    const float2* x = (const float2*)d_in[0];
    float4* out = (float4*)d_out;

    int total_threads = B * C4 * H * J;  // 4,194,304
    int block = 512;
    int grid = total_threads / block;    // 8192
    wav_unpack_kernel<<<grid, block>>>(x, out);
}